// round 1
// baseline (speedup 1.0000x reference)
#include <cuda_runtime.h>

#define N_NODES 4096
#define C_IN    256
#define C_OUT   256
#define BATCH   8
#define M_TOTAL (BATCH * N_NODES)
#define CAP     256   // max nnz per adjacency row we support (mean ~41, 33 sigma margin)

// ---------------- device scratch (no allocations allowed) ----------------
__device__ float g_dis[2][N_NODES];
__device__ int   g_nnz[2][N_NODES];
__device__ int   g_cj[2][N_NODES][CAP];
__device__ float g_cv[2][N_NODES][CAP];
__device__ float g_prop[N_NODES][2 * C_OUT];      // [propA | propB] per row
__device__ float g_Weff0[C_IN * C_OUT];           // W0a@Wp_top + W0b@Wp_bot
__device__ float g_Weff1[2 * C_OUT * C_OUT];      // [W1a@Wp_top ; W1b@Wp_bot]
__device__ float g_bias[C_OUT];                   // bc_a@Wp_top + bc_b@Wp_bot + bp

// ---------------- K1: one pass over each adjacency: degree + CSR compact --
__global__ void __launch_bounds__(256) row_scan(const float* __restrict__ adj1,
                                                const float* __restrict__ adj2)
{
    const int i = blockIdx.x;          // row
    const int a = blockIdx.y;          // which adjacency
    const int t = threadIdx.x;
    const float* __restrict__ row = (a == 0 ? adj1 : adj2) + (size_t)i * N_NODES;

    __shared__ int   cnt;
    __shared__ float sdeg[256];
    if (t == 0) cnt = 0;
    __syncthreads();

    float deg = 0.f;
    const float4* r4 = reinterpret_cast<const float4*>(row);
    #pragma unroll
    for (int s = 0; s < 4; s++) {
        int i4 = t + 256 * s;
        float4 v = r4[i4];
        float vv[4] = {v.x, v.y, v.z, v.w};
        int jb = i4 * 4;
        #pragma unroll
        for (int e = 0; e < 4; e++) {
            int j = jb + e;
            float val = vv[e];
            if (j != i && val != 0.f) {      // remove_self_loops + sparsity
                deg += val;
                int p = atomicAdd(&cnt, 1);
                if (p < CAP) { g_cj[a][i][p] = j; g_cv[a][i][p] = val; }
            }
        }
    }
    sdeg[t] = deg;
    __syncthreads();
    for (int s = 128; s > 0; s >>= 1) {
        if (t < s) sdeg[t] += sdeg[t + s];
        __syncthreads();
    }
    if (t == 0) {
        float d = sdeg[0];
        g_dis[a][i] = (d > 0.f) ? rsqrtf(d) : 0.f;
        g_nnz[a][i] = min(cnt, CAP);
    }
}

// ---------------- K2: fold small weights through the projection ----------
// which=0: Weff0 = W0a@Wp_top + W0b@Wp_bot
// which=1: Weff1[0:256]   = W1a@Wp_top
// which=2: Weff1[256:512] = W1b@Wp_bot
__global__ void __launch_bounds__(256) fold_weights(const float* __restrict__ W0a,
                                                    const float* __restrict__ W1a,
                                                    const float* __restrict__ W0b,
                                                    const float* __restrict__ W1b,
                                                    const float* __restrict__ Wp)
{
    const int o = threadIdx.x;
    const int c = blockIdx.x;
    const int which = blockIdx.y;
    float acc = 0.f;
    if (which == 0) {
        #pragma unroll 8
        for (int k = 0; k < 256; k++)
            acc += W0a[c * 256 + k] * Wp[k * 256 + o]
                 + W0b[c * 256 + k] * Wp[(256 + k) * 256 + o];
        g_Weff0[c * 256 + o] = acc;
    } else if (which == 1) {
        #pragma unroll 8
        for (int k = 0; k < 256; k++)
            acc += W1a[c * 256 + k] * Wp[k * 256 + o];
        g_Weff1[c * 256 + o] = acc;
    } else {
        #pragma unroll 8
        for (int k = 0; k < 256; k++)
            acc += W1b[c * 256 + k] * Wp[(256 + k) * 256 + o];
        g_Weff1[(256 + c) * 256 + o] = acc;
    }
}

__global__ void __launch_bounds__(256) fold_bias(const float* __restrict__ bca,
                                                 const float* __restrict__ bcb,
                                                 const float* __restrict__ bp,
                                                 const float* __restrict__ Wp)
{
    const int o = threadIdx.x;
    float acc = bp[o];
    #pragma unroll 8
    for (int k = 0; k < 256; k++)
        acc += bca[k] * Wp[k * 256 + o] + bcb[k] * Wp[(256 + k) * 256 + o];
    g_bias[o] = acc;
}

// ---------------- K3: sparse propagation  prop = -(Ahat @ x[:N]) ---------
__global__ void __launch_bounds__(256) prop_kernel(const float* __restrict__ x)
{
    const int i = blockIdx.x;
    const int a = blockIdx.y;
    const int t = threadIdx.x;          // channel

    __shared__ int   sj[CAP];
    __shared__ float sv[CAP];
    const int nnz = g_nnz[a][i];
    for (int e = t; e < nnz; e += 256) {
        int j = g_cj[a][i][e];
        sj[e] = j;
        sv[e] = g_cv[a][i][e] * g_dis[a][j];   // a_ij * dis_j
    }
    __syncthreads();

    float acc = 0.f;
    for (int e = 0; e < nnz; e++)
        acc += sv[e] * x[(size_t)sj[e] * C_IN + t];

    g_prop[i][a * C_OUT + t] = -g_dis[a][i] * acc;
}

// ---------------- K4: tiled fp32 GEMM  C (+)= A@B (+ bias) ---------------
template <int BM, int BN, int BK, int TM, int TN>
__global__ void __launch_bounds__(256) gemm_f32(float* __restrict__ C,
                                                const float* __restrict__ A,
                                                const float* __restrict__ B,
                                                int K, int lda, int ldb, int ldc,
                                                const float* __restrict__ bias,
                                                int accumulate)
{
    __shared__ float As[BK][BM];
    __shared__ float Bs[BK][BN];

    const int tid = threadIdx.x;
    const int rowBase = blockIdx.x * BM;
    const int colBase = blockIdx.y * BN;
    const int tx = tid & 15;     // 16 col groups
    const int ty = tid >> 4;     // 16 row groups

    float acc[TM][TN];
    #pragma unroll
    for (int i = 0; i < TM; i++)
        #pragma unroll
        for (int j = 0; j < TN; j++) acc[i][j] = 0.f;

    for (int k0 = 0; k0 < K; k0 += BK) {
        // load A tile (transposed into shared)
        #pragma unroll
        for (int l = 0; l < (BM * BK) / 1024; l++) {
            int idx = tid + l * 256;
            int ar = idx >> 2;
            int ac = (idx & 3) << 2;
            float4 av = *reinterpret_cast<const float4*>(
                &A[(size_t)(rowBase + ar) * lda + k0 + ac]);
            As[ac + 0][ar] = av.x;
            As[ac + 1][ar] = av.y;
            As[ac + 2][ar] = av.z;
            As[ac + 3][ar] = av.w;
        }
        // load B tile
        #pragma unroll
        for (int l = 0; l < (BK * BN) / 1024; l++) {
            int idx = tid + l * 256;
            int br = idx >> 4;
            int bc = (idx & 15) << 2;
            *reinterpret_cast<float4*>(&Bs[br][bc]) =
                *reinterpret_cast<const float4*>(&B[(size_t)(k0 + br) * ldb + colBase + bc]);
        }
        __syncthreads();

        #pragma unroll
        for (int k = 0; k < BK; k++) {
            float ra[TM], rb[TN];
            #pragma unroll
            for (int i = 0; i < TM; i++) ra[i] = As[k][ty * TM + i];
            #pragma unroll
            for (int j = 0; j < TN; j++) rb[j] = Bs[k][tx * TN + j];
            #pragma unroll
            for (int i = 0; i < TM; i++)
                #pragma unroll
                for (int j = 0; j < TN; j++)
                    acc[i][j] += ra[i] * rb[j];
        }
        __syncthreads();
    }

    #pragma unroll
    for (int i = 0; i < TM; i++) {
        int r = rowBase + ty * TM + i;
        #pragma unroll
        for (int j = 0; j < TN; j++) {
            int c = colBase + tx * TN + j;
            float v = acc[i][j];
            if (bias) v += bias[c];
            size_t off = (size_t)r * ldc + c;
            if (accumulate) C[off] += v;
            else            C[off] = v;
        }
    }
}

// ---------------- launcher ----------------
extern "C" void kernel_launch(void* const* d_in, const int* in_sizes, int n_in,
                              void* d_out, int out_size)
{
    const float* x    = (const float*)d_in[0];
    const float* adj1 = (const float*)d_in[1];
    const float* adj2 = (const float*)d_in[2];
    const float* W0a  = (const float*)d_in[3];
    const float* W1a  = (const float*)d_in[4];
    const float* bca  = (const float*)d_in[5];
    const float* W0b  = (const float*)d_in[6];
    const float* W1b  = (const float*)d_in[7];
    const float* bcb  = (const float*)d_in[8];
    const float* Wp   = (const float*)d_in[9];
    const float* bp   = (const float*)d_in[10];
    float* out = (float*)d_out;

    float *p_prop, *p_W0, *p_W1, *p_bias;
    cudaGetSymbolAddress((void**)&p_prop, g_prop);
    cudaGetSymbolAddress((void**)&p_W0,   g_Weff0);
    cudaGetSymbolAddress((void**)&p_W1,   g_Weff1);
    cudaGetSymbolAddress((void**)&p_bias, g_bias);

    // 1. adjacency pass: degrees + CSR compaction (both adjacencies)
    row_scan<<<dim3(N_NODES, 2), 256>>>(adj1, adj2);

    // 2. fold projection into Cheb weights (independent of 1)
    fold_weights<<<dim3(256, 3), 256>>>(W0a, W1a, W0b, W1b, Wp);
    fold_bias<<<1, 256>>>(bca, bcb, bp, Wp);

    // 3. sparse propagation: prop[i] = [-(Ahat1@x)[i] | -(Ahat2@x)[i]]
    prop_kernel<<<dim3(N_NODES, 2), 256>>>(x);

    // 4. out = x_flat @ Weff0 + bias      [32768 x 256 x 256]
    gemm_f32<128, 64, 16, 8, 4><<<dim3(M_TOTAL / 128, C_OUT / 64), 256>>>(
        out, x, p_W0, C_IN, C_IN, C_OUT, C_OUT, p_bias, 0);

    // 5. out[:4096] += [propA|propB] @ Weff1   [4096 x 256 x 512]
    gemm_f32<64, 64, 16, 4, 4><<<dim3(N_NODES / 64, C_OUT / 64), 256>>>(
        out, p_prop, p_W1, 2 * C_OUT, 2 * C_OUT, C_OUT, C_OUT, nullptr, 1);
}